// round 1
// baseline (speedup 1.0000x reference)
#include <cuda_runtime.h>

#define BATCH 128
#define SEQ   4096
#define NPOS  (BATCH * SEQ)

// Scratch for the cumsum (temp_seq). __device__ global: no allocation.
__device__ float g_temp[NPOS];

// Accurate fast tanh: tanh(x) = sign(x) * (1 - e^{-2|x|}) / (1 + e^{-2|x|})
// Divisor in [1,2] -> __fdividef is safe and exact enough (~1e-7 rel err).
__device__ __forceinline__ float fast_tanh(float x) {
    float ax = fabsf(x);
    float t  = __expf(-2.0f * ax);
    float r  = __fdividef(1.0f - t, 1.0f + t);
    return copysignf(r, x);
}

// ---------------------------------------------------------------------------
// Kernel 1: per-batch inclusive cumsum of delta_x[..., 2] plus init temp.
// One block per batch row; 512 threads x 8 elements = 4096.
// ---------------------------------------------------------------------------
__global__ void scan_kernel(const float* __restrict__ delta_x) {
    __shared__ float ssum[512];
    const int b = blockIdx.x;
    const int t = threadIdx.x;
    const float* dx = delta_x + (size_t)b * SEQ * 6;

    const int s0 = t * 8;
    float v[8];
    float run = 0.0f;
#pragma unroll
    for (int k = 0; k < 8; k++) {
        run += dx[(s0 + k) * 6 + 2];
        v[k] = run;  // inclusive prefix within thread
    }
    ssum[t] = run;
    __syncthreads();

    // Hillis-Steele inclusive scan over 512 thread-sums
#pragma unroll
    for (int off = 1; off < 512; off <<= 1) {
        float x = ssum[t];
        float y = (t >= off) ? ssum[t - off] : 0.0f;
        __syncthreads();
        ssum[t] = x + y;
        __syncthreads();
    }

    const float init = dx[5];  // delta_x[b, 0, 5]
    const float base = (t > 0 ? ssum[t - 1] : 0.0f) + init;

    float* tp = g_temp + (size_t)b * SEQ;
#pragma unroll
    for (int k = 0; k < 8; k++) tp[s0 + k] = base + v[k];
}

// ---------------------------------------------------------------------------
// Kernel 2: fused per-position MLP. 1 thread = 1 position.
// Weights staged in shared memory (broadcast reads, Wa1/Wb1 transposed for
// vectorized LDS.128 along K).
// ---------------------------------------------------------------------------
__global__ void __launch_bounds__(256, 2)
msc_kernel(const float* __restrict__ h_prev, const float* __restrict__ delta_x,
           const float* __restrict__ Wa0, const float* __restrict__ ba0,
           const float* __restrict__ Wb0, const float* __restrict__ bb0,
           const float* __restrict__ Wa1, const float* __restrict__ ba1,
           const float* __restrict__ Wb1, const float* __restrict__ bb1,
           const float* __restrict__ W_alpha, const float* __restrict__ b_alpha,
           const float* __restrict__ W_beta,  const float* __restrict__ b_beta,
           const float* __restrict__ W_gamma, const float* __restrict__ b_gamma,
           const float* __restrict__ W_c,     const float* __restrict__ b_c,
           const float* __restrict__ W_out,
           float* __restrict__ out)
{
    __shared__ __align__(16) float sWa0[9 * 32];
    __shared__ __align__(16) float sWb0[9 * 32];
    __shared__ __align__(16) float sWa1T[32 * 32];  // [j][i]
    __shared__ __align__(16) float sWb1T[32 * 32];  // [j][i]
    __shared__ __align__(16) float sWh[32 * 8];     // per i: alpha,beta,gamma,c0..c4
    __shared__ float sba0[32], sbb0[32], sba1[32], sbb1[32];
    __shared__ float sbh[8];
    __shared__ float sWout[5];

    const int tid = threadIdx.x;

    for (int k = tid; k < 9 * 32; k += 256) { sWa0[k] = Wa0[k]; sWb0[k] = Wb0[k]; }
    for (int k = tid; k < 32; k += 256) {
        sba0[k] = ba0[k]; sbb0[k] = bb0[k];
        sba1[k] = ba1[k]; sbb1[k] = bb1[k];
    }
    for (int k = tid; k < 1024; k += 256) {
        int i = k >> 5, j = k & 31;
        sWa1T[j * 32 + i] = Wa1[k];
        sWb1T[j * 32 + i] = Wb1[k];
    }
    for (int k = tid; k < 32; k += 256) {
        sWh[k * 8 + 0] = W_alpha[k];
        sWh[k * 8 + 1] = W_beta[k];
        sWh[k * 8 + 2] = W_gamma[k];
#pragma unroll
        for (int d = 0; d < 5; d++) sWh[k * 8 + 3 + d] = W_c[k * 5 + d];
    }
    if (tid == 0) {
        sbh[0] = b_alpha[0]; sbh[1] = b_beta[0]; sbh[2] = b_gamma[0];
#pragma unroll
        for (int d = 0; d < 5; d++) sbh[3 + d] = b_c[d];
#pragma unroll
        for (int d = 0; d < 5; d++) sWout[d] = W_out[d];
    }
    __syncthreads();

    const int idx = blockIdx.x * 256 + tid;
    if (idx >= NPOS) return;

    // ---- inputs ----
    const float* hp = h_prev + (size_t)idx * 5;
    const float* dx = delta_x + (size_t)idx * 6;
    float l[9];
#pragma unroll
    for (int d = 0; d < 5; d++) l[d] = hp[d];
    const float d0 = dx[0], d1 = dx[1], d2 = dx[2];
    l[5] = g_temp[idx];
    {
        float nrm = sqrtf(d0 * d0 + d1 * d1 + d2 * d2);
        nrm = fmaxf(nrm, 1e-7f);
        float inv = __fdividef(1.0f, nrm);
        l[6] = d0 * inv; l[7] = d1 * inv; l[8] = d2 * inv;
    }

    // ---- layer 0: h = tanh(l@Wa0+ba0) * tanh(l@Wb0+bb0) ----
    float acc[32], h[32];
#pragma unroll
    for (int j = 0; j < 32; j++) acc[j] = sba0[j];
#pragma unroll
    for (int i = 0; i < 9; i++) {
        const float li = l[i];
        const float4* w = (const float4*)(sWa0 + i * 32);
#pragma unroll
        for (int q = 0; q < 8; q++) {
            float4 wv = w[q];
            acc[4 * q + 0] = fmaf(li, wv.x, acc[4 * q + 0]);
            acc[4 * q + 1] = fmaf(li, wv.y, acc[4 * q + 1]);
            acc[4 * q + 2] = fmaf(li, wv.z, acc[4 * q + 2]);
            acc[4 * q + 3] = fmaf(li, wv.w, acc[4 * q + 3]);
        }
    }
#pragma unroll
    for (int j = 0; j < 32; j++) h[j] = fast_tanh(acc[j]);
#pragma unroll
    for (int j = 0; j < 32; j++) acc[j] = sbb0[j];
#pragma unroll
    for (int i = 0; i < 9; i++) {
        const float li = l[i];
        const float4* w = (const float4*)(sWb0 + i * 32);
#pragma unroll
        for (int q = 0; q < 8; q++) {
            float4 wv = w[q];
            acc[4 * q + 0] = fmaf(li, wv.x, acc[4 * q + 0]);
            acc[4 * q + 1] = fmaf(li, wv.y, acc[4 * q + 1]);
            acc[4 * q + 2] = fmaf(li, wv.z, acc[4 * q + 2]);
            acc[4 * q + 3] = fmaf(li, wv.w, acc[4 * q + 3]);
        }
    }
#pragma unroll
    for (int j = 0; j < 32; j++) h[j] *= fast_tanh(acc[j]);

    // ---- layer 1: h2 = tanh(h@Wa1+ba1) * tanh(h@Wb1+bb1), j-outer ----
    float h2[32];
#pragma unroll
    for (int j = 0; j < 32; j++) {
        float va = sba1[j], vb = sbb1[j];
        const float4* wa = (const float4*)(sWa1T + j * 32);
        const float4* wb = (const float4*)(sWb1T + j * 32);
#pragma unroll
        for (int q = 0; q < 8; q++) {
            float4 A = wa[q];
            float4 Bv = wb[q];
            va = fmaf(h[4 * q + 0], A.x, va);
            va = fmaf(h[4 * q + 1], A.y, va);
            va = fmaf(h[4 * q + 2], A.z, va);
            va = fmaf(h[4 * q + 3], A.w, va);
            vb = fmaf(h[4 * q + 0], Bv.x, vb);
            vb = fmaf(h[4 * q + 1], Bv.y, vb);
            vb = fmaf(h[4 * q + 2], Bv.z, vb);
            vb = fmaf(h[4 * q + 3], Bv.w, vb);
        }
        h2[j] = fast_tanh(va) * fast_tanh(vb);
    }

    // ---- heads: [alpha, beta, gamma, c0..c4] ----
    float acc8[8];
#pragma unroll
    for (int k = 0; k < 8; k++) acc8[k] = sbh[k];
#pragma unroll
    for (int i = 0; i < 32; i++) {
        const float hi = h2[i];
        float4 w0 = *(const float4*)(sWh + i * 8);
        float4 w1 = *(const float4*)(sWh + i * 8 + 4);
        acc8[0] = fmaf(hi, w0.x, acc8[0]);
        acc8[1] = fmaf(hi, w0.y, acc8[1]);
        acc8[2] = fmaf(hi, w0.z, acc8[2]);
        acc8[3] = fmaf(hi, w0.w, acc8[3]);
        acc8[4] = fmaf(hi, w1.x, acc8[4]);
        acc8[5] = fmaf(hi, w1.y, acc8[5]);
        acc8[6] = fmaf(hi, w1.z, acc8[6]);
        acc8[7] = fmaf(hi, w1.w, acc8[7]);
    }

    const float alpha = __expf(acc8[0]);
    const float beta  = __expf(acc8[1]);
    const float gamma = __expf(acc8[2]);
    const float zarg  = alpha * fabsf(d0) + beta * d1 + gamma * fabsf(d2);
    const float z     = 1.0f - __expf(-zarg);

    float sigma = 0.0f;
    float* oh = out + (size_t)idx * 5;
#pragma unroll
    for (int d = 0; d < 5; d++) {
        float c  = fast_tanh(acc8[3 + d]);
        float hn = l[d] + z * (c - l[d]);  // (1-z)*h_prev + z*c
        oh[d] = hn;
        sigma = fmaf(hn, sWout[d], sigma);
    }
    out[(size_t)NPOS * 5 + idx] = sigma;
}

extern "C" void kernel_launch(void* const* d_in, const int* in_sizes, int n_in,
                              void* d_out, int out_size) {
    const float* h_prev  = (const float*)d_in[0];
    const float* delta_x = (const float*)d_in[1];
    const float* Wa0     = (const float*)d_in[2];
    const float* ba0     = (const float*)d_in[3];
    const float* Wb0     = (const float*)d_in[4];
    const float* bb0     = (const float*)d_in[5];
    const float* Wa1     = (const float*)d_in[6];
    const float* ba1     = (const float*)d_in[7];
    const float* Wb1     = (const float*)d_in[8];
    const float* bb1     = (const float*)d_in[9];
    const float* W_alpha = (const float*)d_in[10];
    const float* b_alpha = (const float*)d_in[11];
    const float* W_beta  = (const float*)d_in[12];
    const float* b_beta  = (const float*)d_in[13];
    const float* W_gamma = (const float*)d_in[14];
    const float* b_gamma = (const float*)d_in[15];
    const float* W_c     = (const float*)d_in[16];
    const float* b_c     = (const float*)d_in[17];
    const float* W_out   = (const float*)d_in[18];
    float* out = (float*)d_out;

    scan_kernel<<<BATCH, 512>>>(delta_x);
    msc_kernel<<<NPOS / 256, 256>>>(h_prev, delta_x,
                                    Wa0, ba0, Wb0, bb0,
                                    Wa1, ba1, Wb1, bb1,
                                    W_alpha, b_alpha, W_beta, b_beta,
                                    W_gamma, b_gamma, W_c, b_c, W_out,
                                    out);
}